// round 4
// baseline (speedup 1.0000x reference)
#include <cuda_runtime.h>

#define N_NODES 100000
#define N_EDGES 1600000
#define IN_F 128
#define HID_F 64
#define CLS_F 32

// ---------------- scratch (zero-init device globals; no allocation) --------
__device__ float gv56_xw1[N_NODES * HID_F];
__device__ float gv56_h1 [N_NODES * HID_F];
__device__ float gv56_hw2[N_NODES * CLS_F];
__device__ float gv56_dinv[N_NODES];
__device__ int   gv56_cnt[N_NODES];
__device__ int   gv56_rowptr[N_NODES + 1];
__device__ int   gv56_cursor[N_NODES];
__device__ int   gv56_col[N_EDGES];
__device__ int   gv56_is64;

// ---------------- edge_index dtype detection --------------------------------
__global__ __launch_bounds__(32) void k_detect(const void* __restrict__ ei) {
    if (threadIdx.x == 0) {
        const long long* p = (const long long*)ei;
        int ok64 = 1;
        for (int i = 0; i < 2048; i++) {
            long long v = p[i];
            if (v < 0 || v >= (long long)N_NODES) { ok64 = 0; break; }
        }
        gv56_is64 = ok64;
    }
}

__device__ __forceinline__ int edge_at(const void* __restrict__ ei, long long idx) {
    if (gv56_is64) return (int)((const long long*)ei)[idx];
    return ((const int*)ei)[idx];
}

// ---------------- CSR build --------------------------------------------------
__global__ __launch_bounds__(256) void k_zero() {
    int v = blockIdx.x * 256 + threadIdx.x;
    if (v < N_NODES) gv56_cnt[v] = 0;
}

__global__ __launch_bounds__(256) void k_count(const void* __restrict__ ei) {
    int e = blockIdx.x * 256 + threadIdx.x;
    if (e < N_EDGES) {
        int d = edge_at(ei, (long long)N_EDGES + e);
        if ((unsigned)d < (unsigned)N_NODES) atomicAdd(&gv56_cnt[d], 1);
    }
}

__global__ __launch_bounds__(256) void k_dinv() {
    int v = blockIdx.x * 256 + threadIdx.x;
    if (v < N_NODES) gv56_dinv[v] = rsqrtf((float)(gv56_cnt[v] + 1));
}

__global__ __launch_bounds__(1024) void k_scan() {
    __shared__ int sums[1024];
    const int tid = threadIdx.x;
    const int chunk = (N_NODES + 1023) / 1024;
    int start = tid * chunk;
    int end = start + chunk;
    if (end > N_NODES) end = N_NODES;
    if (start > N_NODES) start = N_NODES;

    int s = 0;
    for (int i = start; i < end; i++) s += gv56_cnt[i];
    sums[tid] = s;
    __syncthreads();
    for (int off = 1; off < 1024; off <<= 1) {
        int v = 0;
        if (tid >= off) v = sums[tid - off];
        __syncthreads();
        sums[tid] += v;
        __syncthreads();
    }
    int run = (tid == 0) ? 0 : sums[tid - 1];
    for (int i = start; i < end; i++) {
        gv56_rowptr[i] = run;
        gv56_cursor[i] = run;
        run += gv56_cnt[i];
    }
    if (tid == 0) gv56_rowptr[N_NODES] = sums[1023];
}

__global__ __launch_bounds__(256) void k_fill(const void* __restrict__ ei) {
    int e = blockIdx.x * 256 + threadIdx.x;
    if (e < N_EDGES) {
        int s = edge_at(ei, e);
        int d = edge_at(ei, (long long)N_EDGES + e);
        if ((unsigned)d < (unsigned)N_NODES && (unsigned)s < (unsigned)N_NODES) {
            int slot = atomicAdd(&gv56_cursor[d], 1);
            gv56_col[slot] = s;
        }
    }
}

// ---------------- simple GEMM: one block per node row ------------------------
// Y[v, j] = sum_k X[v,k] * W[k,j].  blockDim = OC threads; X row staged in smem.
__global__ __launch_bounds__(HID_F) void k_gemm1(const float* __restrict__ X,
                                                 const float* __restrict__ W) {
    __shared__ float sx[IN_F];
    int v = blockIdx.x;
    int j = threadIdx.x;
    for (int k = j; k < IN_F; k += HID_F) sx[k] = X[(size_t)v * IN_F + k];
    __syncthreads();
    float acc = 0.0f;
    for (int k = 0; k < IN_F; k++) acc = fmaf(sx[k], W[k * HID_F + j], acc);
    gv56_xw1[(size_t)v * HID_F + j] = acc;
}

__global__ __launch_bounds__(CLS_F) void k_gemm2(const float* __restrict__ W) {
    __shared__ float sh[HID_F];
    int v = blockIdx.x;
    int j = threadIdx.x;
    for (int k = j; k < HID_F; k += CLS_F) sh[k] = gv56_h1[(size_t)v * HID_F + k];
    __syncthreads();
    float acc = 0.0f;
    for (int k = 0; k < HID_F; k++) acc = fmaf(sh[k], W[k * CLS_F + j], acc);
    gv56_hw2[(size_t)v * CLS_F + j] = acc;
}

// ---------------- propagation: one block per node ----------------------------
// out[v,j] = dv*( dv*xw[v,j] + sum_u dinv[u]*xw[u,j] ) + b[j]   (+relu layer 1)
__global__ __launch_bounds__(HID_F) void k_prop1(const float* __restrict__ b) {
    int v = blockIdx.x;
    int j = threadIdx.x;
    float dv = gv56_dinv[v];
    float acc = dv * gv56_xw1[(size_t)v * HID_F + j];
    int p = gv56_rowptr[v];
    int e = gv56_rowptr[v + 1];
    for (; p < e; p++) {
        int u = gv56_col[p];
        acc = fmaf(gv56_dinv[u], gv56_xw1[(size_t)u * HID_F + j], acc);
    }
    float o = acc * dv + b[j];
    gv56_h1[(size_t)v * HID_F + j] = fmaxf(o, 0.0f);
}

__global__ __launch_bounds__(CLS_F) void k_prop2(const float* __restrict__ b,
                                                 float* __restrict__ out) {
    int v = blockIdx.x;
    int j = threadIdx.x;
    float dv = gv56_dinv[v];
    float acc = dv * gv56_hw2[(size_t)v * CLS_F + j];
    int p = gv56_rowptr[v];
    int e = gv56_rowptr[v + 1];
    for (; p < e; p++) {
        int u = gv56_col[p];
        acc = fmaf(gv56_dinv[u], gv56_hw2[(size_t)u * CLS_F + j], acc);
    }
    out[(size_t)v * CLS_F + j] = acc * dv + b[j];
}

// ---------------- launch ------------------------------------------------------
extern "C" void kernel_launch(void* const* d_in, const int* in_sizes, int n_in,
                              void* d_out, int out_size) {
    const float* x  = nullptr;
    const void*  ei = nullptr;
    const float* W1 = nullptr;
    const float* b1 = nullptr;
    const float* W2 = nullptr;
    const float* b2 = nullptr;

    for (int i = 0; i < n_in; i++) {
        switch (in_sizes[i]) {
            case N_NODES * IN_F:  x  = (const float*)d_in[i]; break;
            case 2 * N_EDGES:     ei = d_in[i];               break;
            case N_EDGES:         /* edge_attr unused */       break;
            case IN_F * HID_F:    W1 = (const float*)d_in[i]; break;
            case HID_F:           b1 = (const float*)d_in[i]; break;
            case HID_F * CLS_F:   W2 = (const float*)d_in[i]; break;
            case CLS_F:           b2 = (const float*)d_in[i]; break;
            default: break;
        }
    }
    if (!x)  x  = (const float*)d_in[0];
    if (!ei) ei = d_in[1];
    if (!W1 && n_in > 3) W1 = (const float*)d_in[3];
    if (!b1 && n_in > 4) b1 = (const float*)d_in[4];
    if (!W2 && n_in > 5) W2 = (const float*)d_in[5];
    if (!b2 && n_in > 6) b2 = (const float*)d_in[6];

    float* out = (float*)d_out;

    k_detect<<<1, 32>>>(ei);
    k_zero  <<<(N_NODES + 255) / 256, 256>>>();
    k_count <<<(N_EDGES + 255) / 256, 256>>>(ei);
    k_dinv  <<<(N_NODES + 255) / 256, 256>>>();
    k_scan  <<<1, 1024>>>();
    k_fill  <<<(N_EDGES + 255) / 256, 256>>>(ei);

    k_gemm1<<<N_NODES, HID_F>>>(x, W1);
    k_prop1<<<N_NODES, HID_F>>>(b1);

    k_gemm2<<<N_NODES, CLS_F>>>(W2);
    k_prop2<<<N_NODES, CLS_F>>>(b2, out);
}

// round 5
// speedup vs baseline: 1.4466x; 1.4466x over previous
#include <cuda_runtime.h>

#define N_NODES 100000
#define N_EDGES 1600000
#define IN_F 128
#define HID_F 64
#define CLS_F 32

// ---------------- scratch (16B-aligned for vector access) ------------------
__device__ __align__(16) float gv56_xw1[N_NODES * HID_F];
__device__ __align__(16) float gv56_hw2[N_NODES * CLS_F];
__device__ __align__(16) float gv56_dinv[N_NODES];
__device__ int   gv56_cnt[N_NODES];
__device__ int   gv56_rowptr[N_NODES + 1];
__device__ int   gv56_cursor[N_NODES];
__device__ int   gv56_col[N_EDGES];
__device__ int   gv56_is64;

// ---------------- edge_index dtype detection --------------------------------
__global__ __launch_bounds__(32) void k_detect(const void* __restrict__ ei) {
    if (threadIdx.x == 0) {
        const long long* p = (const long long*)ei;
        int ok64 = 1;
        for (int i = 0; i < 2048; i++) {
            long long v = p[i];
            if (v < 0 || v >= (long long)N_NODES) { ok64 = 0; break; }
        }
        gv56_is64 = ok64;
    }
}

__device__ __forceinline__ int edge_at(const void* __restrict__ ei, long long idx) {
    if (gv56_is64) return (int)((const long long*)ei)[idx];
    return ((const int*)ei)[idx];
}

// ---------------- CSR build --------------------------------------------------
__global__ __launch_bounds__(256) void k_zero() {
    int v = blockIdx.x * 256 + threadIdx.x;
    if (v < N_NODES) gv56_cnt[v] = 0;
}

__global__ __launch_bounds__(256) void k_count(const void* __restrict__ ei) {
    int e = blockIdx.x * 256 + threadIdx.x;
    if (e < N_EDGES) {
        int d = edge_at(ei, (long long)N_EDGES + e);
        if ((unsigned)d < (unsigned)N_NODES) atomicAdd(&gv56_cnt[d], 1);
    }
}

__global__ __launch_bounds__(256) void k_dinv() {
    int v = blockIdx.x * 256 + threadIdx.x;
    if (v < N_NODES) gv56_dinv[v] = rsqrtf((float)(gv56_cnt[v] + 1));
}

__global__ __launch_bounds__(1024) void k_scan() {
    __shared__ int sums[1024];
    const int tid = threadIdx.x;
    const int chunk = (N_NODES + 1023) / 1024;
    int start = tid * chunk;
    int end = start + chunk;
    if (end > N_NODES) end = N_NODES;
    if (start > N_NODES) start = N_NODES;

    int s = 0;
    for (int i = start; i < end; i++) s += gv56_cnt[i];
    sums[tid] = s;
    __syncthreads();
    for (int off = 1; off < 1024; off <<= 1) {
        int v = 0;
        if (tid >= off) v = sums[tid - off];
        __syncthreads();
        sums[tid] += v;
        __syncthreads();
    }
    int run = (tid == 0) ? 0 : sums[tid - 1];
    for (int i = start; i < end; i++) {
        gv56_rowptr[i] = run;
        gv56_cursor[i] = run;
        run += gv56_cnt[i];
    }
    if (tid == 0) gv56_rowptr[N_NODES] = sums[1023];
}

__global__ __launch_bounds__(256) void k_fill(const void* __restrict__ ei) {
    int e = blockIdx.x * 256 + threadIdx.x;
    if (e < N_EDGES) {
        int s = edge_at(ei, e);
        int d = edge_at(ei, (long long)N_EDGES + e);
        if ((unsigned)d < (unsigned)N_NODES && (unsigned)s < (unsigned)N_NODES) {
            int slot = atomicAdd(&gv56_cursor[d], 1);
            gv56_col[slot] = s;
        }
    }
}

// ---------------- GEMM1: xw1 = X @ W1  (64 nodes x 64 cols per block) -------
__global__ __launch_bounds__(256) void k_gemm1(const float* __restrict__ X,
                                               const float* __restrict__ W) {
    __shared__ __align__(16) float sW[IN_F * HID_F];   // 32 KB, staged once
    __shared__ __align__(16) float sX[64 * 36];        // 9 KB, 32-k chunks

    const int tid = threadIdx.x;
    const int m0 = blockIdx.x * 64;
    const int ty = tid >> 4;   // 0..15 : rows ty*4 .. ty*4+3
    const int tx = tid & 15;   // 0..15 : cols tx*4 .. tx*4+3

    for (int i = tid; i < IN_F * HID_F / 4; i += 256)
        ((float4*)sW)[i] = ((const float4*)W)[i];

    float acc[4][4];
#pragma unroll
    for (int i = 0; i < 4; i++)
#pragma unroll
        for (int j = 0; j < 4; j++) acc[i][j] = 0.0f;

    for (int kt = 0; kt < IN_F; kt += 32) {
        __syncthreads();
        for (int i = tid; i < 64 * 8; i += 256) {
            int r = i >> 3, c4 = i & 7;
            int gr = m0 + r;
            float4 v = make_float4(0.f, 0.f, 0.f, 0.f);
            if (gr < N_NODES)
                v = *(const float4*)&X[(size_t)gr * IN_F + kt + c4 * 4];
            *(float4*)&sX[r * 36 + c4 * 4] = v;
        }
        __syncthreads();

#pragma unroll
        for (int kk = 0; kk < 32; kk++) {
            float4 w4 = ((const float4*)(sW + (kt + kk) * HID_F))[tx];
            float a0 = sX[(ty * 4 + 0) * 36 + kk];
            float a1 = sX[(ty * 4 + 1) * 36 + kk];
            float a2 = sX[(ty * 4 + 2) * 36 + kk];
            float a3 = sX[(ty * 4 + 3) * 36 + kk];
            acc[0][0] = fmaf(a0, w4.x, acc[0][0]);
            acc[0][1] = fmaf(a0, w4.y, acc[0][1]);
            acc[0][2] = fmaf(a0, w4.z, acc[0][2]);
            acc[0][3] = fmaf(a0, w4.w, acc[0][3]);
            acc[1][0] = fmaf(a1, w4.x, acc[1][0]);
            acc[1][1] = fmaf(a1, w4.y, acc[1][1]);
            acc[1][2] = fmaf(a1, w4.z, acc[1][2]);
            acc[1][3] = fmaf(a1, w4.w, acc[1][3]);
            acc[2][0] = fmaf(a2, w4.x, acc[2][0]);
            acc[2][1] = fmaf(a2, w4.y, acc[2][1]);
            acc[2][2] = fmaf(a2, w4.z, acc[2][2]);
            acc[2][3] = fmaf(a2, w4.w, acc[2][3]);
            acc[3][0] = fmaf(a3, w4.x, acc[3][0]);
            acc[3][1] = fmaf(a3, w4.y, acc[3][1]);
            acc[3][2] = fmaf(a3, w4.z, acc[3][2]);
            acc[3][3] = fmaf(a3, w4.w, acc[3][3]);
        }
    }

#pragma unroll
    for (int i = 0; i < 4; i++) {
        int gr = m0 + ty * 4 + i;
        if (gr < N_NODES) {
            float4 o = make_float4(acc[i][0], acc[i][1], acc[i][2], acc[i][3]);
            *(float4*)&gv56_xw1[(size_t)gr * HID_F + tx * 4] = o;
        }
    }
}

// ---------------- fused prop1 + ReLU + GEMM2 --------------------------------
// warp per node: aggregate xw1 over in-neighbors (float2/lane), relu+bias,
// then hw2[v] = h @ W2 computed by the same warp from smem.
__global__ __launch_bounds__(256) void k_prop1g2(const float* __restrict__ b1,
                                                 const float* __restrict__ W2) {
    __shared__ __align__(16) float sh[8][HID_F];
    const int warp = threadIdx.x >> 5;
    const int lane = threadIdx.x & 31;
    const int v = blockIdx.x * 8 + warp;
    if (v >= N_NODES) return;

    const float2* __restrict__ xw2 = (const float2*)gv56_xw1;
    float dv = gv56_dinv[v];
    float2 self = xw2[(size_t)v * 32 + lane];
    float ax = dv * self.x;
    float ay = dv * self.y;

    int p = gv56_rowptr[v];
    const int e = gv56_rowptr[v + 1];
    for (; p + 4 <= e; p += 4) {
        int u0 = gv56_col[p],     u1 = gv56_col[p + 1];
        int u2 = gv56_col[p + 2], u3 = gv56_col[p + 3];
        float d0 = gv56_dinv[u0], d1 = gv56_dinv[u1];
        float d2 = gv56_dinv[u2], d3 = gv56_dinv[u3];
        float2 f0 = xw2[(size_t)u0 * 32 + lane];
        float2 f1 = xw2[(size_t)u1 * 32 + lane];
        float2 f2 = xw2[(size_t)u2 * 32 + lane];
        float2 f3 = xw2[(size_t)u3 * 32 + lane];
        ax += d0 * f0.x + d1 * f1.x + d2 * f2.x + d3 * f3.x;
        ay += d0 * f0.y + d1 * f1.y + d2 * f2.y + d3 * f3.y;
    }
    for (; p < e; p++) {
        int u = gv56_col[p];
        float du = gv56_dinv[u];
        float2 f = xw2[(size_t)u * 32 + lane];
        ax += du * f.x;
        ay += du * f.y;
    }

    float2 bb = ((const float2*)b1)[lane];
    sh[warp][2 * lane]     = fmaxf(ax * dv + bb.x, 0.0f);
    sh[warp][2 * lane + 1] = fmaxf(ay * dv + bb.y, 0.0f);
    __syncwarp();

    // per-node gemm2: lane j computes hw2[v][j] = sum_k h[k] * W2[k][j]
    float o = 0.0f;
#pragma unroll 8
    for (int k = 0; k < HID_F; k++)
        o = fmaf(sh[warp][k], W2[k * CLS_F + lane], o);
    gv56_hw2[(size_t)v * CLS_F + lane] = o;
}

// ---------------- prop2: out = norm-aggregate(hw2) + b2 ---------------------
__global__ __launch_bounds__(256) void k_prop2(const float* __restrict__ b2,
                                               float* __restrict__ out) {
    const int warp = threadIdx.x >> 5;
    const int lane = threadIdx.x & 31;
    const int v = blockIdx.x * 8 + warp;
    if (v >= N_NODES) return;

    float dv = gv56_dinv[v];
    float acc = dv * gv56_hw2[(size_t)v * CLS_F + lane];

    int p = gv56_rowptr[v];
    const int e = gv56_rowptr[v + 1];
    for (; p + 4 <= e; p += 4) {
        int u0 = gv56_col[p],     u1 = gv56_col[p + 1];
        int u2 = gv56_col[p + 2], u3 = gv56_col[p + 3];
        float d0 = gv56_dinv[u0], d1 = gv56_dinv[u1];
        float d2 = gv56_dinv[u2], d3 = gv56_dinv[u3];
        float f0 = gv56_hw2[(size_t)u0 * CLS_F + lane];
        float f1 = gv56_hw2[(size_t)u1 * CLS_F + lane];
        float f2 = gv56_hw2[(size_t)u2 * CLS_F + lane];
        float f3 = gv56_hw2[(size_t)u3 * CLS_F + lane];
        acc += d0 * f0 + d1 * f1 + d2 * f2 + d3 * f3;
    }
    for (; p < e; p++) {
        int u = gv56_col[p];
        acc += gv56_dinv[u] * gv56_hw2[(size_t)u * CLS_F + lane];
    }
    out[(size_t)v * CLS_F + lane] = acc * dv + b2[lane];
}

// ---------------- launch ------------------------------------------------------
extern "C" void kernel_launch(void* const* d_in, const int* in_sizes, int n_in,
                              void* d_out, int out_size) {
    const float* x  = nullptr;
    const void*  ei = nullptr;
    const float* W1 = nullptr;
    const float* b1 = nullptr;
    const float* W2 = nullptr;
    const float* b2 = nullptr;

    for (int i = 0; i < n_in; i++) {
        switch (in_sizes[i]) {
            case N_NODES * IN_F:  x  = (const float*)d_in[i]; break;
            case 2 * N_EDGES:     ei = d_in[i];               break;
            case N_EDGES:         /* edge_attr unused */       break;
            case IN_F * HID_F:    W1 = (const float*)d_in[i]; break;
            case HID_F:           b1 = (const float*)d_in[i]; break;
            case HID_F * CLS_F:   W2 = (const float*)d_in[i]; break;
            case CLS_F:           b2 = (const float*)d_in[i]; break;
            default: break;
        }
    }
    if (!x)  x  = (const float*)d_in[0];
    if (!ei) ei = d_in[1];
    if (!W1 && n_in > 3) W1 = (const float*)d_in[3];
    if (!b1 && n_in > 4) b1 = (const float*)d_in[4];
    if (!W2 && n_in > 5) W2 = (const float*)d_in[5];
    if (!b2 && n_in > 6) b2 = (const float*)d_in[6];

    float* out = (float*)d_out;

    k_detect<<<1, 32>>>(ei);
    k_zero  <<<(N_NODES + 255) / 256, 256>>>();
    k_count <<<(N_EDGES + 255) / 256, 256>>>(ei);
    k_dinv  <<<(N_NODES + 255) / 256, 256>>>();
    k_scan  <<<1, 1024>>>();
    k_fill  <<<(N_EDGES + 255) / 256, 256>>>(ei);

    k_gemm1  <<<(N_NODES + 63) / 64, 256>>>(x, W1);
    k_prop1g2<<<(N_NODES + 7) / 8, 256>>>(b1, W2);
    k_prop2  <<<(N_NODES + 7) / 8, 256>>>(b2, out);
}

// round 6
// speedup vs baseline: 2.6244x; 1.8142x over previous
#include <cuda_runtime.h>

#define N_NODES 100000
#define N_EDGES 1600000
#define IN_F 128
#define HID_F 64
#define CLS_F 32
#define NBLK 391   // ceil(N_NODES/256)

// ---------------- scratch (16B-aligned for vector access) ------------------
__device__ __align__(16) float gv56_xw1[N_NODES * HID_F];
__device__ __align__(16) float gv56_hw2[N_NODES * CLS_F];
__device__ __align__(16) float gv56_dinv[N_NODES];
__device__ int   gv56_cnt[N_NODES];
__device__ int   gv56_rowptr[N_NODES + 1];
__device__ int   gv56_cursor[N_NODES];
__device__ int   gv56_col[N_EDGES];
__device__ int   gv56_bsum[512];
__device__ int   gv56_boff[512];
__device__ int   gv56_is64;

// ---------------- init: zero cnt + detect edge dtype ------------------------
__global__ __launch_bounds__(256) void k_init(const void* __restrict__ ei) {
    if (blockIdx.x == NBLK) {
        if (threadIdx.x == 0) {
            const long long* p = (const long long*)ei;
            int ok64 = 1;
            for (int i = 0; i < 2048; i++) {
                long long v = p[i];
                if (v < 0 || v >= (long long)N_NODES) { ok64 = 0; break; }
            }
            gv56_is64 = ok64;
        }
        return;
    }
    int v = blockIdx.x * 256 + threadIdx.x;
    if (v < N_NODES) gv56_cnt[v] = 0;
}

__device__ __forceinline__ int edge_at(const void* __restrict__ ei, long long idx) {
    if (gv56_is64) return (int)((const long long*)ei)[idx];
    return ((const int*)ei)[idx];
}

// ---------------- CSR build --------------------------------------------------
__global__ __launch_bounds__(256) void k_count(const void* __restrict__ ei) {
    int e = blockIdx.x * 256 + threadIdx.x;
    if (e < N_EDGES) {
        int d = edge_at(ei, (long long)N_EDGES + e);
        if ((unsigned)d < (unsigned)N_NODES) atomicAdd(&gv56_cnt[d], 1);
    }
}

// phase 1: per-block sums (coalesced reduce)
__global__ __launch_bounds__(256) void k_bsum() {
    __shared__ int red[8];
    int i = blockIdx.x * 256 + threadIdx.x;
    int v = (i < N_NODES) ? gv56_cnt[i] : 0;
#pragma unroll
    for (int o = 16; o; o >>= 1) v += __shfl_down_sync(0xffffffffu, v, o);
    if ((threadIdx.x & 31) == 0) red[threadIdx.x >> 5] = v;
    __syncthreads();
    if (threadIdx.x < 8) {
        int s = red[threadIdx.x];
#pragma unroll
        for (int o = 4; o; o >>= 1) s += __shfl_down_sync(0xffu, s, o);
        if (threadIdx.x == 0) gv56_bsum[blockIdx.x] = s;
    }
}

// phase 2: exclusive scan of block sums (tiny, 1 block)
__global__ __launch_bounds__(512) void k_boff() {
    __shared__ int s[512];
    int t = threadIdx.x;
    int v = (t < NBLK) ? gv56_bsum[t] : 0;
    s[t] = v;
    __syncthreads();
    for (int off = 1; off < 512; off <<= 1) {
        int a = 0;
        if (t >= off) a = s[t - off];
        __syncthreads();
        s[t] += a;
        __syncthreads();
    }
    if (t < NBLK) gv56_boff[t] = s[t] - v;
}

// phase 3: per-block exclusive scan + offset -> rowptr/cursor, plus dinv
__global__ __launch_bounds__(256) void k_scan3() {
    __shared__ int s[256];
    int t = threadIdx.x;
    int i = blockIdx.x * 256 + t;
    int v = (i < N_NODES) ? gv56_cnt[i] : 0;
    s[t] = v;
    __syncthreads();
    for (int off = 1; off < 256; off <<= 1) {
        int a = 0;
        if (t >= off) a = s[t - off];
        __syncthreads();
        s[t] += a;
        __syncthreads();
    }
    if (i < N_NODES) {
        int r = gv56_boff[blockIdx.x] + s[t] - v;
        gv56_rowptr[i] = r;
        gv56_cursor[i] = r;
        gv56_dinv[i] = rsqrtf((float)(v + 1));
        if (i == N_NODES - 1) gv56_rowptr[N_NODES] = r + v;
    }
}

__global__ __launch_bounds__(256) void k_fill(const void* __restrict__ ei) {
    int e = blockIdx.x * 256 + threadIdx.x;
    if (e < N_EDGES) {
        int s = edge_at(ei, e);
        int d = edge_at(ei, (long long)N_EDGES + e);
        if ((unsigned)d < (unsigned)N_NODES && (unsigned)s < (unsigned)N_NODES) {
            int slot = atomicAdd(&gv56_cursor[d], 1);
            gv56_col[slot] = s;
        }
    }
}

// ---------------- GEMM1: xw1 = X @ W1  (64 nodes x 64 cols per block) -------
__global__ __launch_bounds__(256) void k_gemm1(const float* __restrict__ X,
                                               const float* __restrict__ W) {
    __shared__ __align__(16) float sW[IN_F * HID_F];   // 32 KB, staged once
    __shared__ __align__(16) float sX[64 * 36];        // 9 KB, 32-k chunks

    const int tid = threadIdx.x;
    const int m0 = blockIdx.x * 64;
    const int ty = tid >> 4;
    const int tx = tid & 15;

    for (int i = tid; i < IN_F * HID_F / 4; i += 256)
        ((float4*)sW)[i] = ((const float4*)W)[i];

    float acc[4][4];
#pragma unroll
    for (int i = 0; i < 4; i++)
#pragma unroll
        for (int j = 0; j < 4; j++) acc[i][j] = 0.0f;

    for (int kt = 0; kt < IN_F; kt += 32) {
        __syncthreads();
        for (int i = tid; i < 64 * 8; i += 256) {
            int r = i >> 3, c4 = i & 7;
            int gr = m0 + r;
            float4 v = make_float4(0.f, 0.f, 0.f, 0.f);
            if (gr < N_NODES)
                v = *(const float4*)&X[(size_t)gr * IN_F + kt + c4 * 4];
            *(float4*)&sX[r * 36 + c4 * 4] = v;
        }
        __syncthreads();

#pragma unroll
        for (int kk = 0; kk < 32; kk++) {
            float4 w4 = ((const float4*)(sW + (kt + kk) * HID_F))[tx];
            float a0 = sX[(ty * 4 + 0) * 36 + kk];
            float a1 = sX[(ty * 4 + 1) * 36 + kk];
            float a2 = sX[(ty * 4 + 2) * 36 + kk];
            float a3 = sX[(ty * 4 + 3) * 36 + kk];
            acc[0][0] = fmaf(a0, w4.x, acc[0][0]);
            acc[0][1] = fmaf(a0, w4.y, acc[0][1]);
            acc[0][2] = fmaf(a0, w4.z, acc[0][2]);
            acc[0][3] = fmaf(a0, w4.w, acc[0][3]);
            acc[1][0] = fmaf(a1, w4.x, acc[1][0]);
            acc[1][1] = fmaf(a1, w4.y, acc[1][1]);
            acc[1][2] = fmaf(a1, w4.z, acc[1][2]);
            acc[1][3] = fmaf(a1, w4.w, acc[1][3]);
            acc[2][0] = fmaf(a2, w4.x, acc[2][0]);
            acc[2][1] = fmaf(a2, w4.y, acc[2][1]);
            acc[2][2] = fmaf(a2, w4.z, acc[2][2]);
            acc[2][3] = fmaf(a2, w4.w, acc[2][3]);
            acc[3][0] = fmaf(a3, w4.x, acc[3][0]);
            acc[3][1] = fmaf(a3, w4.y, acc[3][1]);
            acc[3][2] = fmaf(a3, w4.z, acc[3][2]);
            acc[3][3] = fmaf(a3, w4.w, acc[3][3]);
        }
    }

#pragma unroll
    for (int i = 0; i < 4; i++) {
        int gr = m0 + ty * 4 + i;
        if (gr < N_NODES) {
            float4 o = make_float4(acc[i][0], acc[i][1], acc[i][2], acc[i][3]);
            *(float4*)&gv56_xw1[(size_t)gr * HID_F + tx * 4] = o;
        }
    }
}

// ---------------- fused prop1 + ReLU + GEMM2 --------------------------------
__global__ __launch_bounds__(256) void k_prop1g2(const float* __restrict__ b1,
                                                 const float* __restrict__ W2) {
    __shared__ __align__(16) float sh[8][HID_F];
    const int warp = threadIdx.x >> 5;
    const int lane = threadIdx.x & 31;
    const int v = blockIdx.x * 8 + warp;
    if (v >= N_NODES) return;

    const float2* __restrict__ xw2 = (const float2*)gv56_xw1;
    float dv = gv56_dinv[v];
    float2 self = xw2[(size_t)v * 32 + lane];
    float ax = dv * self.x;
    float ay = dv * self.y;

    int p = gv56_rowptr[v];
    const int e = gv56_rowptr[v + 1];
    for (; p + 4 <= e; p += 4) {
        int u0 = gv56_col[p],     u1 = gv56_col[p + 1];
        int u2 = gv56_col[p + 2], u3 = gv56_col[p + 3];
        float d0 = gv56_dinv[u0], d1 = gv56_dinv[u1];
        float d2 = gv56_dinv[u2], d3 = gv56_dinv[u3];
        float2 f0 = xw2[(size_t)u0 * 32 + lane];
        float2 f1 = xw2[(size_t)u1 * 32 + lane];
        float2 f2 = xw2[(size_t)u2 * 32 + lane];
        float2 f3 = xw2[(size_t)u3 * 32 + lane];
        ax += d0 * f0.x + d1 * f1.x + d2 * f2.x + d3 * f3.x;
        ay += d0 * f0.y + d1 * f1.y + d2 * f2.y + d3 * f3.y;
    }
    for (; p < e; p++) {
        int u = gv56_col[p];
        float du = gv56_dinv[u];
        float2 f = xw2[(size_t)u * 32 + lane];
        ax += du * f.x;
        ay += du * f.y;
    }

    float2 bb = ((const float2*)b1)[lane];
    sh[warp][2 * lane]     = fmaxf(ax * dv + bb.x, 0.0f);
    sh[warp][2 * lane + 1] = fmaxf(ay * dv + bb.y, 0.0f);
    __syncwarp();

    float o = 0.0f;
#pragma unroll 8
    for (int k = 0; k < HID_F; k++)
        o = fmaf(sh[warp][k], W2[k * CLS_F + lane], o);
    gv56_hw2[(size_t)v * CLS_F + lane] = o;
}

// ---------------- prop2: out = norm-aggregate(hw2) + b2 ---------------------
__global__ __launch_bounds__(256) void k_prop2(const float* __restrict__ b2,
                                               float* __restrict__ out) {
    const int warp = threadIdx.x >> 5;
    const int lane = threadIdx.x & 31;
    const int v = blockIdx.x * 8 + warp;
    if (v >= N_NODES) return;

    float dv = gv56_dinv[v];
    float acc = dv * gv56_hw2[(size_t)v * CLS_F + lane];

    int p = gv56_rowptr[v];
    const int e = gv56_rowptr[v + 1];
    for (; p + 4 <= e; p += 4) {
        int u0 = gv56_col[p],     u1 = gv56_col[p + 1];
        int u2 = gv56_col[p + 2], u3 = gv56_col[p + 3];
        float d0 = gv56_dinv[u0], d1 = gv56_dinv[u1];
        float d2 = gv56_dinv[u2], d3 = gv56_dinv[u3];
        float f0 = gv56_hw2[(size_t)u0 * CLS_F + lane];
        float f1 = gv56_hw2[(size_t)u1 * CLS_F + lane];
        float f2 = gv56_hw2[(size_t)u2 * CLS_F + lane];
        float f3 = gv56_hw2[(size_t)u3 * CLS_F + lane];
        acc += d0 * f0 + d1 * f1 + d2 * f2 + d3 * f3;
    }
    for (; p < e; p++) {
        int u = gv56_col[p];
        acc += gv56_dinv[u] * gv56_hw2[(size_t)u * CLS_F + lane];
    }
    out[(size_t)v * CLS_F + lane] = acc * dv + b2[lane];
}

// ---------------- launch ------------------------------------------------------
extern "C" void kernel_launch(void* const* d_in, const int* in_sizes, int n_in,
                              void* d_out, int out_size) {
    const float* x  = nullptr;
    const void*  ei = nullptr;
    const float* W1 = nullptr;
    const float* b1 = nullptr;
    const float* W2 = nullptr;
    const float* b2 = nullptr;

    for (int i = 0; i < n_in; i++) {
        switch (in_sizes[i]) {
            case N_NODES * IN_F:  x  = (const float*)d_in[i]; break;
            case 2 * N_EDGES:     ei = d_in[i];               break;
            case N_EDGES:         /* edge_attr unused */       break;
            case IN_F * HID_F:    W1 = (const float*)d_in[i]; break;
            case HID_F:           b1 = (const float*)d_in[i]; break;
            case HID_F * CLS_F:   W2 = (const float*)d_in[i]; break;
            case CLS_F:           b2 = (const float*)d_in[i]; break;
            default: break;
        }
    }
    if (!x)  x  = (const float*)d_in[0];
    if (!ei) ei = d_in[1];
    if (!W1 && n_in > 3) W1 = (const float*)d_in[3];
    if (!b1 && n_in > 4) b1 = (const float*)d_in[4];
    if (!W2 && n_in > 5) W2 = (const float*)d_in[5];
    if (!b2 && n_in > 6) b2 = (const float*)d_in[6];

    float* out = (float*)d_out;

    k_init <<<NBLK + 1, 256>>>(ei);                 // #1 zero + detect
    k_count<<<(N_EDGES + 255) / 256, 256>>>(ei);    // #2
    k_bsum <<<NBLK, 256>>>();                       // #3
    k_gemm1<<<(N_NODES + 63) / 64, 256>>>(x, W1);   // #4  (profiled slot)
    k_boff <<<1, 512>>>();                          // #5
    k_scan3<<<NBLK, 256>>>();                       // #6  (also writes dinv)
    k_fill <<<(N_EDGES + 255) / 256, 256>>>(ei);    // #7
    k_prop1g2<<<(N_NODES + 7) / 8, 256>>>(b1, W2);  // #8
    k_prop2  <<<(N_NODES + 7) / 8, 256>>>(b2, out); // #9
}